// round 6
// baseline (speedup 1.0000x reference)
#include <cuda_runtime.h>
#include <math.h>

#define Nn 50000
#define Ee 800000
#define Rr 64
#define Dd 64
#define Ll 4
#define Bb 2
#define Kk 32

#define DEG_PAD 53248          // 13 * 4096, covers Nn+1

// scratch (no allocations allowed)
__device__ float g_xA[Bb * Nn * Dd];   // 25.6 MB  (ping)
__device__ float g_xB[Bb * Nn * Dd];   // 25.6 MB  (pong)
__device__ float g_Wt[Ll * 2 * Dd * Dd]; // pre-transposed+swizzled weights
__device__ int   g_deg[DEG_PAD];       // histogram -> rowptr (in place)
__device__ int   g_cursor[Nn];         // rowptr copy, consumed by fill
__device__ int2  g_epack[Ee];          // (src, edge_type) sorted by dst

#define FMA2(d, a, b, c) asm("fma.rn.f32x2 %0, %1, %2, %3;" : "=l"(d) : "l"(a), "l"(b), "l"(c))

// ---------------- CSR build ----------------
__global__ void k_zero() {
    int i = blockIdx.x * blockDim.x + threadIdx.x;
    if (i < DEG_PAD / 4) reinterpret_cast<int4*>(g_deg)[i] = make_int4(0, 0, 0, 0);
}

__global__ void k_hist(const int* __restrict__ ei) {
    int t = blockIdx.x * blockDim.x + threadIdx.x;
    if (t >= Ee / 4) return;
    int4 d4 = reinterpret_cast<const int4*>(ei + Ee)[t];
    atomicAdd(&g_deg[d4.x + 1], 1);
    atomicAdd(&g_deg[d4.y + 1], 1);
    atomicAdd(&g_deg[d4.z + 1], 1);
    atomicAdd(&g_deg[d4.w + 1], 1);
}

// transpose + swizzle all layer weights: W[l][j][d] -> g_Wt[l][d*128 + ((j>>2 ^ (d&31))<<2) + (j&3)]
__global__ void k_wprep(const float* __restrict__ W) {
    int idx = blockIdx.x * blockDim.x + threadIdx.x;
    if (idx >= Ll * 2 * Dd * Dd) return;
    int l = idx >> 13;
    int rem = idx & 8191;
    int j = rem >> 6;
    int d = rem & 63;
    g_Wt[(l << 13) + d * 128 + (((j >> 2) ^ (d & 31)) << 2) + (j & 3)] = W[idx];
}

// single-block inclusive scan over g_deg[0..DEG_PAD), 4 elems/thread, 13 chunks.
// Also seeds g_cursor with rowptr starts.
__global__ void k_scan() {
    __shared__ int wsum[32];
    __shared__ int carry_s;
    int t = threadIdx.x, lane = t & 31, w = t >> 5;
    if (t == 0) carry_s = 0;
    __syncthreads();
    for (int base = 0; base < DEG_PAD; base += 4096) {
        int i0 = base + t * 4;
        int4 v = *reinterpret_cast<const int4*>(&g_deg[i0]);
        int s1 = v.x, s2 = s1 + v.y, s3 = s2 + v.z, s4 = s3 + v.w;
        int x = s4;
        #pragma unroll
        for (int off = 1; off < 32; off <<= 1) {
            int u = __shfl_up_sync(0xffffffffu, x, off);
            if (lane >= off) x += u;
        }
        if (lane == 31) wsum[w] = x;
        __syncthreads();
        if (w == 0) {
            int y = wsum[lane];
            #pragma unroll
            for (int off = 1; off < 32; off <<= 1) {
                int u = __shfl_up_sync(0xffffffffu, y, off);
                if (lane >= off) y += u;
            }
            wsum[lane] = y;
        }
        __syncthreads();
        int off0 = carry_s + ((w > 0) ? wsum[w - 1] : 0) + (x - s4);
        int4 o = make_int4(off0 + s1, off0 + s2, off0 + s3, off0 + s4);
        *reinterpret_cast<int4*>(&g_deg[i0]) = o;
        if (i0 + 0 < Nn) g_cursor[i0 + 0] = o.x;
        if (i0 + 1 < Nn) g_cursor[i0 + 1] = o.y;
        if (i0 + 2 < Nn) g_cursor[i0 + 2] = o.z;
        if (i0 + 3 < Nn) g_cursor[i0 + 3] = o.w;
        __syncthreads();
        if (t == 1023) carry_s = off0 + s4;
        __syncthreads();
    }
}

// fused: CSR fill (4 edges/thread) + x init (float4/thread) into g_xA
__global__ void k_fillinit(const int* __restrict__ ei, const int* __restrict__ et,
                           const float* __restrict__ be, const float* __restrict__ rel,
                           const int* __restrict__ h_index, const int* __restrict__ r_index) {
    const int FILLT = Ee / 4;   // 200000
    int t = blockIdx.x * blockDim.x + threadIdx.x;
    if (t < FILLT) {
        int4 s4 = reinterpret_cast<const int4*>(ei)[t];
        int4 d4 = reinterpret_cast<const int4*>(ei + Ee)[t];
        int4 t4 = reinterpret_cast<const int4*>(et)[t];
        int p0 = atomicAdd(&g_cursor[d4.x], 1);
        int p1 = atomicAdd(&g_cursor[d4.y], 1);
        int p2 = atomicAdd(&g_cursor[d4.z], 1);
        int p3 = atomicAdd(&g_cursor[d4.w], 1);
        g_epack[p0] = make_int2(s4.x, t4.x);
        g_epack[p1] = make_int2(s4.y, t4.y);
        g_epack[p2] = make_int2(s4.z, t4.z);
        g_epack[p3] = make_int2(s4.w, t4.w);
    } else {
        int idx = t - FILLT;
        if (idx >= Bb * Nn * 16) return;
        int d4i = idx & 15;
        int bn = idx >> 4;
        int b = (bn >= Nn) ? 1 : 0;
        int n = bn - b * Nn;
        float4 v = reinterpret_cast<const float4*>(be)[idx];
        if (n == h_index[b]) {
            float4 q = reinterpret_cast<const float4*>(rel)[((b * Rr + r_index[b]) << 4) + d4i];
            v.x += q.x; v.y += q.y; v.z += q.z; v.w += q.w;
        }
        reinterpret_cast<float4*>(g_xA)[idx] = v;
    }
}

// ---------------- fused layer: gather (into smem) + dense + LN + residual ----------------
// Block owns 32 nodes = 64 rows (both batches). Reads xin, writes xout (ping-pong).
// sIn row r (r<32: b=0 node n0+r; r>=32: b=1 node n0+r-32): cols 0..63 = x, 64..127 = agg.
__global__ __launch_bounds__(256) void k_layer(
        const float* __restrict__ xin, float* __restrict__ xout,
        const float* __restrict__ Wt, const float* __restrict__ bias,
        const float* __restrict__ gam, const float* __restrict__ bet,
        const float* __restrict__ be, const float* __restrict__ rel,
        const int* __restrict__ h_index, const int* __restrict__ r_index) {
    extern __shared__ float smem[];
    float* sWt = smem;               // 64 * 128 floats, pre-swizzled (32 KB)
    float* sIn = smem + 64 * 128;    // 64 rows * 128 floats          (32 KB)

    const int tid  = threadIdx.x;
    const int w    = tid >> 5;
    const int lane = tid & 31;
    const int n0   = blockIdx.x * 32;

    // ---- phase A: stage W (linear float4 copy) + x rows ----
    {
        const float4* Wv = reinterpret_cast<const float4*>(Wt);
        float4* sWv = reinterpret_cast<float4*>(sWt);
        #pragma unroll
        for (int k = 0; k < 8; k++) sWv[k * 256 + tid] = Wv[k * 256 + tid];
    }
    {
        // 64 rows x 16 float4 (x half only) = 1024 slots; 4 per thread
        #pragma unroll
        for (int k = 0; k < 4; k++) {
            int pos = k * 256 + tid;
            int r   = pos >> 4;          // local row 0..63
            int c4  = pos & 15;
            int b   = r >> 5;
            int n   = n0 + (r & 31);
            float4 v = make_float4(0.f, 0.f, 0.f, 0.f);
            if (n < Nn) v = *reinterpret_cast<const float4*>(&xin[((size_t)(b * Nn + n) << 6) + (c4 << 2)]);
            *reinterpret_cast<float4*>(&sIn[r * 128 + (c4 << 2)]) = v;
        }
    }

    // ---- phase B: gather agg into smem (warp w handles nodes n0 + w*4 .. +3) ----
    {
        int b = lane >> 4;           // batch for this half-warp
        int c = (lane & 15) << 2;    // float4 column within D=64
        const int base_x = (b * Nn) << 6;
        const int base_r = (b * Rr) << 6;
        const int hidx = h_index[b];
        #pragma unroll
        for (int i = 0; i < 4; i++) {
            int nl = w * 4 + i;          // node-local 0..31
            int n = n0 + nl;
            if (n >= Nn) break;
            float4 acc = *reinterpret_cast<const float4*>(&be[((size_t)(b * Nn + n) << 6) + c]);
            if (n == hidx) {
                float4 q = __ldg(reinterpret_cast<const float4*>(&rel[((b * Rr + r_index[b]) << 6) + c]));
                acc.x += q.x; acc.y += q.y; acc.z += q.z; acc.w += q.w;
            }
            int s = g_deg[n], e = g_deg[n + 1];
            int k = s;

            #define EDGE_LOAD(ek, xv, rv)                                                            \
                float4 xv = __ldg(reinterpret_cast<const float4*>(&xin[base_x + (ek.x << 6) + c]));  \
                float4 rv = __ldg(reinterpret_cast<const float4*>(&rel[base_r + (ek.y << 6) + c]));
            #define EDGE_FMA(xv, rv)                                                                 \
                acc.x += xv.x * rv.x; acc.y += xv.y * rv.y;                                          \
                acc.z += xv.z * rv.z; acc.w += xv.w * rv.w;

            if (k + 3 < e) {
                int2 E0 = g_epack[k];
                int2 E1 = g_epack[k + 1];
                int2 E2 = g_epack[k + 2];
                int2 E3 = g_epack[k + 3];
                while (k + 3 < e) {
                    int nk = k + 4;
                    int p0 = nk     < e ? nk     : e - 1;
                    int p1 = nk + 1 < e ? nk + 1 : e - 1;
                    int p2 = nk + 2 < e ? nk + 2 : e - 1;
                    int p3 = nk + 3 < e ? nk + 3 : e - 1;
                    int2 F0 = g_epack[p0];
                    int2 F1 = g_epack[p1];
                    int2 F2 = g_epack[p2];
                    int2 F3 = g_epack[p3];
                    EDGE_LOAD(E0, x0, r0)
                    EDGE_LOAD(E1, x1, r1)
                    EDGE_LOAD(E2, x2, r2)
                    EDGE_LOAD(E3, x3, r3)
                    EDGE_FMA(x0, r0)
                    EDGE_FMA(x1, r1)
                    EDGE_FMA(x2, r2)
                    EDGE_FMA(x3, r3)
                    E0 = F0; E1 = F1; E2 = F2; E3 = F3;
                    k = nk;
                }
            }
            for (; k < e; k++) {
                int2 e0 = g_epack[k];
                EDGE_LOAD(e0, x0, r0)
                EDGE_FMA(x0, r0)
            }
            #undef EDGE_LOAD
            #undef EDGE_FMA

            int r = b * 32 + nl;
            *reinterpret_cast<float4*>(&sIn[r * 128 + 64 + c]) = acc;
        }
    }
    __syncthreads();

    // ---- phase C: dense. 8 rows per warp; lane owns outputs {lane, lane+32} ----
    const int r0 = w * 8;
    unsigned long long acc0[8], acc1[8];
    #pragma unroll
    for (int i = 0; i < 8; i++) { acc0[i] = 0ULL; acc1[i] = 0ULL; }

    const float* wb0 = sWt + lane * 128;
    const float* wb1 = sWt + (lane + 32) * 128;

    #pragma unroll 4
    for (int j4 = 0; j4 < 32; j4++) {
        int off = (j4 ^ lane) << 2;
        ulonglong2 wa  = *reinterpret_cast<const ulonglong2*>(wb0 + off);
        ulonglong2 wbv = *reinterpret_cast<const ulonglong2*>(wb1 + off);
        #pragma unroll
        for (int i = 0; i < 8; i++) {
            ulonglong2 in = *reinterpret_cast<const ulonglong2*>(&sIn[(r0 + i) * 128 + (j4 << 2)]);
            FMA2(acc0[i], in.x, wa.x, acc0[i]);
            FMA2(acc0[i], in.y, wa.y, acc0[i]);
            FMA2(acc1[i], in.x, wbv.x, acc1[i]);
            FMA2(acc1[i], in.y, wbv.y, acc1[i]);
        }
    }

    float bx = bias[lane], by = bias[lane + 32];
    float gx = gam[lane],  gy = gam[lane + 32];
    float tx = bet[lane],  ty = bet[lane + 32];

    #pragma unroll
    for (int i = 0; i < 8; i++) {
        int r = r0 + i;
        int b = r >> 5;
        int n = n0 + (r & 31);
        float2 a0, a1;
        asm("mov.b64 {%0,%1}, %2;" : "=f"(a0.x), "=f"(a0.y) : "l"(acc0[i]));
        asm("mov.b64 {%0,%1}, %2;" : "=f"(a1.x), "=f"(a1.y) : "l"(acc1[i]));
        float o0 = a0.x + a0.y + bx;
        float o1 = a1.x + a1.y + by;

        float s = o0 + o1;
        #pragma unroll
        for (int o = 16; o > 0; o >>= 1) s += __shfl_xor_sync(0xffffffffu, s, o);
        float mu = s * (1.0f / 64.0f);
        float c0 = o0 - mu, c1 = o1 - mu;
        float q = c0 * c0 + c1 * c1;
        #pragma unroll
        for (int o = 16; o > 0; o >>= 1) q += __shfl_xor_sync(0xffffffffu, q, o);
        float inv = rsqrtf(q * (1.0f / 64.0f) + 1e-5f);

        if (n < Nn) {
            float x0 = sIn[r * 128 + lane];
            float x1 = sIn[r * 128 + lane + 32];
            size_t grow = ((size_t)(b * Nn + n) << 6);
            xout[grow + lane]      = fmaxf(c0 * inv * gx + tx, 0.0f) + x0;
            xout[grow + lane + 32] = fmaxf(c1 * inv * gy + ty, 0.0f) + x1;
        }
    }
}

// ---------------- output MLP ----------------
__global__ void k_out(const float* __restrict__ x,
                      const int* __restrict__ t_index, const int* __restrict__ r_index,
                      const float* __restrict__ rel,
                      const float* __restrict__ w1, const float* __restrict__ b1,
                      const float* __restrict__ w2, const float* __restrict__ b2,
                      float* __restrict__ out) {
    __shared__ float feat[2 * Dd];
    __shared__ float red[64];
    int b = blockIdx.x >> 5;   // Kk == 32
    int k = blockIdx.x & 31;
    int tid = threadIdx.x;     // 0..63
    int t = t_index[b * Kk + k];
    feat[tid]      = x[((size_t)(b * Nn + t)) * Dd + tid];
    feat[Dd + tid] = rel[(b * Rr + r_index[b]) * Dd + tid];
    __syncthreads();
    float h = b1[tid];
    #pragma unroll
    for (int j = 0; j < 2 * Dd; j++) h += feat[j] * w1[j * Dd + tid];
    h = fmaxf(h, 0.0f);
    red[tid] = h * w2[tid];
    __syncthreads();
    if (tid < 32) {
        float v = red[tid] + red[tid + 32];
        #pragma unroll
        for (int o = 16; o > 0; o >>= 1) v += __shfl_xor_sync(0xffffffffu, v, o);
        if (tid == 0) out[blockIdx.x] = v + b2[0];
    }
}

extern "C" void kernel_launch(void* const* d_in, const int* in_sizes, int n_in,
                              void* d_out, int out_size) {
    const int*   edge_index = (const int*)d_in[0];
    const int*   edge_type  = (const int*)d_in[1];
    const int*   h_index    = (const int*)d_in[2];
    const int*   r_index    = (const int*)d_in[3];
    const int*   t_index    = (const int*)d_in[4];
    const float* rel        = (const float*)d_in[5];
    const float* be         = (const float*)d_in[6];
    const float* lW         = (const float*)d_in[7];
    const float* lb         = (const float*)d_in[8];
    const float* lng        = (const float*)d_in[9];
    const float* lnb        = (const float*)d_in[10];
    const float* w1         = (const float*)d_in[11];
    const float* b1         = (const float*)d_in[12];
    const float* w2         = (const float*)d_in[13];
    const float* b2         = (const float*)d_in[14];
    float* out = (float*)d_out;

    const int zero_blocks   = (DEG_PAD / 4 + 255) / 256;          // 52
    const int hist_blocks   = (Ee / 4 + 255) / 256;               // 782
    const int wprep_blocks  = (Ll * 2 * Dd * Dd + 255) / 256;     // 128
    const int fi_threads    = Ee / 4 + Bb * Nn * 16;              // 1.8M
    const int fi_blocks     = (fi_threads + 255) / 256;           // 7032
    const int layer_blocks  = (Nn + 31) / 32;                     // 1563
    const int layer_smem    = 2 * 64 * 128 * sizeof(float);       // 64 KB

    static int attr_set = 0;
    if (!attr_set) {
        cudaFuncSetAttribute(k_layer, cudaFuncAttributeMaxDynamicSharedMemorySize, layer_smem);
        attr_set = 1;
    }

    // get device addresses of ping-pong buffers (host-side, no sync needed: statics)
    float* xA; cudaGetSymbolAddress((void**)&xA, g_xA);
    float* xB; cudaGetSymbolAddress((void**)&xB, g_xB);
    float* Wt; cudaGetSymbolAddress((void**)&Wt, g_Wt);

    // CSR build + W prep + x init (per launch; deterministic inputs)
    k_zero<<<zero_blocks, 256>>>();
    k_hist<<<hist_blocks, 256>>>(edge_index);
    k_wprep<<<wprep_blocks, 256>>>(lW);
    k_scan<<<1, 1024>>>();
    k_fillinit<<<fi_blocks, 256>>>(edge_index, edge_type, be, rel, h_index, r_index);

    const float* xin = xA;
    float* xout = xB;
    for (int l = 0; l < Ll; l++) {
        k_layer<<<layer_blocks, 256, layer_smem>>>(xin, xout,
                                                   Wt + l * 2 * Dd * Dd, lb + l * Dd,
                                                   lng + l * Dd, lnb + l * Dd,
                                                   be, rel, h_index, r_index);
        const float* tmp = xout;
        xout = (float*)xin;
        xin = tmp;
    }

    k_out<<<Bb * Kk, 64>>>(xin, t_index, r_index, rel, w1, b1, w2, b2, out);
}

// round 7
// speedup vs baseline: 1.0498x; 1.0498x over previous
#include <cuda_runtime.h>
#include <math.h>

#define Nn 50000
#define Ee 800000
#define Rr 64
#define Dd 64
#define Ll 4
#define Bb 2
#define Kk 32

#define DEG_PAD 53248          // 13 * 4096, covers Nn+1
#define SCAN_BLOCKS 13

// scratch (no allocations allowed)
__device__ float g_x[Bb * Nn * Dd];      // 25.6 MB
__device__ float g_agg[Bb * Nn * Dd];    // 25.6 MB
__device__ float g_Wt[Ll * 2 * Dd * Dd]; // pre-transposed+swizzled weights
__device__ int   g_deg[DEG_PAD];         // histogram -> rowptr (in place)
__device__ int   g_cursor[Nn];           // rowptr copy, consumed by fill
__device__ int2  g_epack[Ee];            // (src, edge_type) sorted by dst
__device__ int   g_scan_inc[SCAN_BLOCKS];
__device__ volatile int g_scan_flag[SCAN_BLOCKS];

#define FMA2(d, a, b, c) asm("fma.rn.f32x2 %0, %1, %2, %3;" : "=l"(d) : "l"(a), "l"(b), "l"(c))

// ---------------- CSR build ----------------
__global__ void k_zero() {
    int i = blockIdx.x * blockDim.x + threadIdx.x;
    if (i < DEG_PAD / 4) reinterpret_cast<int4*>(g_deg)[i] = make_int4(0, 0, 0, 0);
    if (i < SCAN_BLOCKS) { g_scan_flag[i] = 0; g_scan_inc[i] = 0; }
}

__global__ void k_hist(const int* __restrict__ ei) {
    int t = blockIdx.x * blockDim.x + threadIdx.x;
    if (t >= Ee / 4) return;
    int4 d4 = reinterpret_cast<const int4*>(ei + Ee)[t];
    atomicAdd(&g_deg[d4.x + 1], 1);
    atomicAdd(&g_deg[d4.y + 1], 1);
    atomicAdd(&g_deg[d4.z + 1], 1);
    atomicAdd(&g_deg[d4.w + 1], 1);
}

// decoupled-lookback inclusive scan over g_deg[0..DEG_PAD).
// 13 blocks x 1024 threads x 4 elems. All blocks co-resident -> spin is safe.
// Also seeds g_cursor with rowptr starts.
__global__ __launch_bounds__(1024) void k_scan() {
    __shared__ int wsum[32];
    __shared__ int s_excl;
    const int blk = blockIdx.x;
    const int t = threadIdx.x, lane = t & 31, w = t >> 5;
    const int i0 = blk * 4096 + t * 4;

    int4 v = *reinterpret_cast<const int4*>(&g_deg[i0]);
    int s1 = v.x, s2 = s1 + v.y, s3 = s2 + v.z, s4 = s3 + v.w;
    int x = s4;
    #pragma unroll
    for (int off = 1; off < 32; off <<= 1) {
        int u = __shfl_up_sync(0xffffffffu, x, off);
        if (lane >= off) x += u;
    }
    if (lane == 31) wsum[w] = x;
    __syncthreads();
    if (w == 0) {
        int y = wsum[lane];
        #pragma unroll
        for (int off = 1; off < 32; off <<= 1) {
            int u = __shfl_up_sync(0xffffffffu, y, off);
            if (lane >= off) y += u;
        }
        wsum[lane] = y;
    }
    __syncthreads();
    int warp_excl = (w > 0) ? wsum[w - 1] : 0;
    int block_total = wsum[31];

    if (t == 0) {
        int excl = 0;
        if (blk > 0) {
            while (g_scan_flag[blk - 1] == 0) { }
            excl = *((volatile int*)&g_scan_inc[blk - 1]);
        }
        g_scan_inc[blk] = excl + block_total;
        __threadfence();
        g_scan_flag[blk] = 1;
        s_excl = excl;
    }
    __syncthreads();

    int off0 = s_excl + warp_excl + (x - s4);
    int4 o = make_int4(off0 + s1, off0 + s2, off0 + s3, off0 + s4);
    *reinterpret_cast<int4*>(&g_deg[i0]) = o;
    if (i0 + 0 < Nn) g_cursor[i0 + 0] = o.x;
    if (i0 + 1 < Nn) g_cursor[i0 + 1] = o.y;
    if (i0 + 2 < Nn) g_cursor[i0 + 2] = o.z;
    if (i0 + 3 < Nn) g_cursor[i0 + 3] = o.w;
}

// fused: CSR fill (8 edges/thread) + x init (float4/thread) + W prep (scalar)
__global__ void k_fillinit(const int* __restrict__ ei, const int* __restrict__ et,
                           const float* __restrict__ be, const float* __restrict__ rel,
                           const int* __restrict__ h_index, const int* __restrict__ r_index,
                           const float* __restrict__ W) {
    const int FILLT = Ee / 8;              // 100000
    const int INITT = Bb * Nn * 16;        // 1600000
    int t = blockIdx.x * blockDim.x + threadIdx.x;
    if (t < FILLT) {
        #pragma unroll
        for (int h = 0; h < 2; h++) {
            int q = t * 2 + h;
            int4 s4 = reinterpret_cast<const int4*>(ei)[q];
            int4 d4 = reinterpret_cast<const int4*>(ei + Ee)[q];
            int4 t4 = reinterpret_cast<const int4*>(et)[q];
            int p0 = atomicAdd(&g_cursor[d4.x], 1);
            int p1 = atomicAdd(&g_cursor[d4.y], 1);
            int p2 = atomicAdd(&g_cursor[d4.z], 1);
            int p3 = atomicAdd(&g_cursor[d4.w], 1);
            g_epack[p0] = make_int2(s4.x, t4.x);
            g_epack[p1] = make_int2(s4.y, t4.y);
            g_epack[p2] = make_int2(s4.z, t4.z);
            g_epack[p3] = make_int2(s4.w, t4.w);
        }
    } else if (t < FILLT + INITT) {
        int idx = t - FILLT;
        int d4i = idx & 15;
        int bn = idx >> 4;
        int b = (bn >= Nn) ? 1 : 0;
        int n = bn - b * Nn;
        float4 v = reinterpret_cast<const float4*>(be)[idx];
        if (n == h_index[b]) {
            float4 q = reinterpret_cast<const float4*>(rel)[((b * Rr + r_index[b]) << 4) + d4i];
            v.x += q.x; v.y += q.y; v.z += q.z; v.w += q.w;
        }
        reinterpret_cast<float4*>(g_x)[idx] = v;
    } else {
        int idx = t - FILLT - INITT;
        if (idx >= Ll * 2 * Dd * Dd) return;
        int l = idx >> 13;
        int rem = idx & 8191;
        int j = rem >> 6;
        int d = rem & 63;
        g_Wt[(l << 13) + d * 128 + (((j >> 2) ^ (d & 31)) << 2) + (j & 3)] = W[idx];
    }
}

// ---------------- gather aggregation (atomic-free) ----------------
// one warp per node, BOTH batches: half-warp = batch, lane owns a float4.
// Software-pipelined epack prefetch.
__global__ __launch_bounds__(256) void k_gather(const float* __restrict__ be,
                                                const float* __restrict__ rel,
                                                const int* __restrict__ h_index,
                                                const int* __restrict__ r_index) {
    int n = blockIdx.x * 8 + (threadIdx.x >> 5);
    if (n >= Nn) return;
    int lane = threadIdx.x & 31;
    int b = lane >> 4;           // batch for this half-warp
    int c = (lane & 15) << 2;    // float4 column offset within D=64

    const size_t row = ((size_t)(b * Nn + n) << 6) + c;
    float4 acc = *reinterpret_cast<const float4*>(&be[row]);
    if (n == h_index[b]) {
        float4 q = __ldg(reinterpret_cast<const float4*>(&rel[((b * Rr + r_index[b]) << 6) + c]));
        acc.x += q.x; acc.y += q.y; acc.z += q.z; acc.w += q.w;
    }

    const int base_x = (b * Nn) << 6;
    const int base_r = (b * Rr) << 6;
    int s = g_deg[n], e = g_deg[n + 1];
    int k = s;

    #define EDGE_LOAD(ek, xv, rv)                                                          \
        float4 xv = __ldg(reinterpret_cast<const float4*>(&g_x[base_x + (ek.x << 6) + c])); \
        float4 rv = __ldg(reinterpret_cast<const float4*>(&rel[base_r + (ek.y << 6) + c]));
    #define EDGE_FMA(xv, rv)                                                               \
        acc.x += xv.x * rv.x; acc.y += xv.y * rv.y;                                        \
        acc.z += xv.z * rv.z; acc.w += xv.w * rv.w;

    if (k + 3 < e) {
        int2 E0 = g_epack[k];
        int2 E1 = g_epack[k + 1];
        int2 E2 = g_epack[k + 2];
        int2 E3 = g_epack[k + 3];
        while (k + 3 < e) {
            int nk = k + 4;
            int p0 = nk     < e ? nk     : e - 1;
            int p1 = nk + 1 < e ? nk + 1 : e - 1;
            int p2 = nk + 2 < e ? nk + 2 : e - 1;
            int p3 = nk + 3 < e ? nk + 3 : e - 1;
            int2 F0 = g_epack[p0];
            int2 F1 = g_epack[p1];
            int2 F2 = g_epack[p2];
            int2 F3 = g_epack[p3];
            EDGE_LOAD(E0, x0, r0)
            EDGE_LOAD(E1, x1, r1)
            EDGE_LOAD(E2, x2, r2)
            EDGE_LOAD(E3, x3, r3)
            EDGE_FMA(x0, r0)
            EDGE_FMA(x1, r1)
            EDGE_FMA(x2, r2)
            EDGE_FMA(x3, r3)
            E0 = F0; E1 = F1; E2 = F2; E3 = F3;
            k = nk;
        }
    }
    for (; k < e; k++) {
        int2 e0 = g_epack[k];
        EDGE_LOAD(e0, x0, r0)
        EDGE_FMA(x0, r0)
    }
    #undef EDGE_LOAD
    #undef EDGE_FMA

    *reinterpret_cast<float4*>(&g_agg[row]) = acc;
}

// ---------------- dense layer: out = relu(LN(concat(x,agg)@W + b)) + x ----------------
// 64 rows/block, 8 rows per warp; lane owns outputs {lane, lane+32}.
// W pre-transposed+swizzled in g_Wt -> staging is a clean float4 copy.
// Accumulators packed f32x2 (even j, odd j) via fma.rn.f32x2.
__global__ void k_dense(const float* __restrict__ Wt, const float* __restrict__ bias,
                        const float* __restrict__ gam, const float* __restrict__ bet) {
    extern __shared__ float smem[];
    float* sWt = smem;               // 64 * 128 floats, pre-swizzled (32 KB)
    float* sIn = smem + 64 * 128;    // 64 rows * 128 floats          (32 KB)

    const int tid  = threadIdx.x;
    const int w    = tid >> 5;
    const int lane = tid & 31;
    const int base = blockIdx.x * 64;

    {
        const float4* Wv = reinterpret_cast<const float4*>(Wt);
        float4* sWv = reinterpret_cast<float4*>(sWt);
        #pragma unroll
        for (int k = 0; k < 8; k++) sWv[k * 256 + tid] = Wv[k * 256 + tid];
    }
    {
        float4* sInv = reinterpret_cast<float4*>(sIn);
        #pragma unroll
        for (int k = 0; k < 8; k++) {
            int pos = k * 256 + tid;
            int r   = pos >> 5;
            int c4  = pos & 31;
            int row = base + r;
            float4 v = make_float4(0.f, 0.f, 0.f, 0.f);
            if (row < Bb * Nn) {
                if (c4 < 16)
                    v = *reinterpret_cast<const float4*>(&g_x[((size_t)row << 6) + (c4 << 2)]);
                else
                    v = *reinterpret_cast<const float4*>(&g_agg[((size_t)row << 6) + ((c4 - 16) << 2)]);
            }
            sInv[pos] = v;
        }
    }
    __syncthreads();

    const int r0 = w * 8;
    unsigned long long acc0[8], acc1[8];
    #pragma unroll
    for (int i = 0; i < 8; i++) { acc0[i] = 0ULL; acc1[i] = 0ULL; }

    const float* wb0 = sWt + lane * 128;
    const float* wb1 = sWt + (lane + 32) * 128;

    #pragma unroll 4
    for (int j4 = 0; j4 < 32; j4++) {
        int off = (j4 ^ lane) << 2;
        ulonglong2 wa  = *reinterpret_cast<const ulonglong2*>(wb0 + off);
        ulonglong2 wbv = *reinterpret_cast<const ulonglong2*>(wb1 + off);
        #pragma unroll
        for (int i = 0; i < 8; i++) {
            ulonglong2 in = *reinterpret_cast<const ulonglong2*>(&sIn[(r0 + i) * 128 + (j4 << 2)]);
            FMA2(acc0[i], in.x, wa.x, acc0[i]);
            FMA2(acc0[i], in.y, wa.y, acc0[i]);
            FMA2(acc1[i], in.x, wbv.x, acc1[i]);
            FMA2(acc1[i], in.y, wbv.y, acc1[i]);
        }
    }

    float bx = bias[lane], by = bias[lane + 32];
    float gx = gam[lane],  gy = gam[lane + 32];
    float tx = bet[lane],  ty = bet[lane + 32];

    #pragma unroll
    for (int i = 0; i < 8; i++) {
        int row = base + r0 + i;
        if (row >= Bb * Nn) break;   // uniform across warp
        float2 a0, a1;
        asm("mov.b64 {%0,%1}, %2;" : "=f"(a0.x), "=f"(a0.y) : "l"(acc0[i]));
        asm("mov.b64 {%0,%1}, %2;" : "=f"(a1.x), "=f"(a1.y) : "l"(acc1[i]));
        float o0 = a0.x + a0.y + bx;
        float o1 = a1.x + a1.y + by;

        float s = o0 + o1;
        #pragma unroll
        for (int o = 16; o > 0; o >>= 1) s += __shfl_xor_sync(0xffffffffu, s, o);
        float mu = s * (1.0f / 64.0f);
        float c0 = o0 - mu, c1 = o1 - mu;
        float q = c0 * c0 + c1 * c1;
        #pragma unroll
        for (int o = 16; o > 0; o >>= 1) q += __shfl_xor_sync(0xffffffffu, q, o);
        float inv = rsqrtf(q * (1.0f / 64.0f) + 1e-5f);

        float x0 = sIn[(r0 + i) * 128 + lane];
        float x1 = sIn[(r0 + i) * 128 + lane + 32];
        g_x[((size_t)row << 6) + lane]      = fmaxf(c0 * inv * gx + tx, 0.0f) + x0;
        g_x[((size_t)row << 6) + lane + 32] = fmaxf(c1 * inv * gy + ty, 0.0f) + x1;
    }
}

// ---------------- output MLP ----------------
__global__ void k_out(const int* __restrict__ t_index, const int* __restrict__ r_index,
                      const float* __restrict__ rel,
                      const float* __restrict__ w1, const float* __restrict__ b1,
                      const float* __restrict__ w2, const float* __restrict__ b2,
                      float* __restrict__ out) {
    __shared__ float feat[2 * Dd];
    __shared__ float red[64];
    int b = blockIdx.x >> 5;   // Kk == 32
    int k = blockIdx.x & 31;
    int tid = threadIdx.x;     // 0..63
    int t = t_index[b * Kk + k];
    feat[tid]      = g_x[((size_t)(b * Nn + t)) * Dd + tid];
    feat[Dd + tid] = rel[(b * Rr + r_index[b]) * Dd + tid];
    __syncthreads();
    float h = b1[tid];
    #pragma unroll
    for (int j = 0; j < 2 * Dd; j++) h += feat[j] * w1[j * Dd + tid];
    h = fmaxf(h, 0.0f);
    red[tid] = h * w2[tid];
    __syncthreads();
    if (tid < 32) {
        float v = red[tid] + red[tid + 32];
        #pragma unroll
        for (int o = 16; o > 0; o >>= 1) v += __shfl_xor_sync(0xffffffffu, v, o);
        if (tid == 0) out[blockIdx.x] = v + b2[0];
    }
}

extern "C" void kernel_launch(void* const* d_in, const int* in_sizes, int n_in,
                              void* d_out, int out_size) {
    const int*   edge_index = (const int*)d_in[0];
    const int*   edge_type  = (const int*)d_in[1];
    const int*   h_index    = (const int*)d_in[2];
    const int*   r_index    = (const int*)d_in[3];
    const int*   t_index    = (const int*)d_in[4];
    const float* rel        = (const float*)d_in[5];
    const float* be         = (const float*)d_in[6];
    const float* lW         = (const float*)d_in[7];
    const float* lb         = (const float*)d_in[8];
    const float* lng        = (const float*)d_in[9];
    const float* lnb        = (const float*)d_in[10];
    const float* w1         = (const float*)d_in[11];
    const float* b1         = (const float*)d_in[12];
    const float* w2         = (const float*)d_in[13];
    const float* b2         = (const float*)d_in[14];
    float* out = (float*)d_out;

    const int zero_blocks   = (DEG_PAD / 4 + 255) / 256;                    // 52
    const int hist_blocks   = (Ee / 4 + 255) / 256;                         // 782
    const int fi_threads    = Ee / 8 + Bb * Nn * 16 + Ll * 2 * Dd * Dd;     // ~1.73M
    const int fi_blocks     = (fi_threads + 255) / 256;
    const int gather_blocks = (Nn + 7) / 8;                                 // 6250
    const int dense_blocks  = (Bb * Nn + 63) / 64;                          // 1563
    const int dense_smem    = 2 * 64 * 128 * sizeof(float);                 // 64 KB

    static int attr_set = 0;
    if (!attr_set) {
        cudaFuncSetAttribute(k_dense, cudaFuncAttributeMaxDynamicSharedMemorySize, dense_smem);
        attr_set = 1;
    }

    float* Wt; cudaGetSymbolAddress((void**)&Wt, g_Wt);

    // CSR build + x init + W prep (per launch; deterministic inputs)
    k_zero<<<zero_blocks, 256>>>();
    k_hist<<<hist_blocks, 256>>>(edge_index);
    k_scan<<<SCAN_BLOCKS, 1024>>>();
    k_fillinit<<<fi_blocks, 256>>>(edge_index, edge_type, be, rel, h_index, r_index, lW);

    for (int l = 0; l < Ll; l++) {
        k_gather<<<gather_blocks, 256>>>(be, rel, h_index, r_index);
        k_dense<<<dense_blocks, 256, dense_smem>>>(Wt + l * 2 * Dd * Dd, lb + l * Dd,
                                                   lng + l * Dd, lnb + l * Dd);
    }

    k_out<<<Bb * Kk, 64>>>(t_index, r_index, rel, w1, b1, w2, b2, out);
}

// round 8
// speedup vs baseline: 1.0588x; 1.0086x over previous
#include <cuda_runtime.h>
#include <math.h>

#define Nn 50000
#define Ee 800000
#define Rr 64
#define Dd 64
#define Ll 4
#define Bb 2
#define Kk 32

#define DEG_PAD 53248          // 13 * 4096, covers Nn+1
#define SCAN_BLOCKS 13

// scratch (no allocations allowed)
__device__ float g_x[Bb * Nn * Dd];      // 25.6 MB
__device__ float g_agg[Bb * Nn * Dd];    // 25.6 MB
__device__ float g_Wt[Ll * 2 * Dd * Dd]; // pre-transposed+swizzled weights
__device__ int   g_deg[DEG_PAD];         // histogram -> rowptr (in place)
__device__ int   g_cursor[Nn];           // rowptr copy, consumed by fill
__device__ int   g_epk[Ee];              // packed (src*64 | et), sorted by dst
__device__ int   g_scan_inc[SCAN_BLOCKS];
__device__ volatile int g_scan_flag[SCAN_BLOCKS];

#define FMA2(d, a, b, c) asm("fma.rn.f32x2 %0, %1, %2, %3;" : "=l"(d) : "l"(a), "l"(b), "l"(c))

// ---------------- CSR build ----------------
__global__ void k_zero() {
    int i = blockIdx.x * blockDim.x + threadIdx.x;
    if (i < DEG_PAD / 4) reinterpret_cast<int4*>(g_deg)[i] = make_int4(0, 0, 0, 0);
    if (i < SCAN_BLOCKS) { g_scan_flag[i] = 0; g_scan_inc[i] = 0; }
}

__global__ void k_hist(const int* __restrict__ ei) {
    int t = blockIdx.x * blockDim.x + threadIdx.x;
    if (t >= Ee / 4) return;
    int4 d4 = reinterpret_cast<const int4*>(ei + Ee)[t];
    atomicAdd(&g_deg[d4.x + 1], 1);
    atomicAdd(&g_deg[d4.y + 1], 1);
    atomicAdd(&g_deg[d4.z + 1], 1);
    atomicAdd(&g_deg[d4.w + 1], 1);
}

// decoupled-lookback inclusive scan over g_deg[0..DEG_PAD).
// 13 blocks x 1024 threads x 4 elems. All blocks co-resident -> spin is safe.
__global__ __launch_bounds__(1024) void k_scan() {
    __shared__ int wsum[32];
    __shared__ int s_excl;
    const int blk = blockIdx.x;
    const int t = threadIdx.x, lane = t & 31, w = t >> 5;
    const int i0 = blk * 4096 + t * 4;

    int4 v = *reinterpret_cast<const int4*>(&g_deg[i0]);
    int s1 = v.x, s2 = s1 + v.y, s3 = s2 + v.z, s4 = s3 + v.w;
    int x = s4;
    #pragma unroll
    for (int off = 1; off < 32; off <<= 1) {
        int u = __shfl_up_sync(0xffffffffu, x, off);
        if (lane >= off) x += u;
    }
    if (lane == 31) wsum[w] = x;
    __syncthreads();
    if (w == 0) {
        int y = wsum[lane];
        #pragma unroll
        for (int off = 1; off < 32; off <<= 1) {
            int u = __shfl_up_sync(0xffffffffu, y, off);
            if (lane >= off) y += u;
        }
        wsum[lane] = y;
    }
    __syncthreads();
    int warp_excl = (w > 0) ? wsum[w - 1] : 0;
    int block_total = wsum[31];

    if (t == 0) {
        int excl = 0;
        if (blk > 0) {
            while (g_scan_flag[blk - 1] == 0) { }
            excl = *((volatile int*)&g_scan_inc[blk - 1]);
        }
        g_scan_inc[blk] = excl + block_total;
        __threadfence();
        g_scan_flag[blk] = 1;
        s_excl = excl;
    }
    __syncthreads();

    int off0 = s_excl + warp_excl + (x - s4);
    int4 o = make_int4(off0 + s1, off0 + s2, off0 + s3, off0 + s4);
    *reinterpret_cast<int4*>(&g_deg[i0]) = o;
    if (i0 + 0 < Nn) g_cursor[i0 + 0] = o.x;
    if (i0 + 1 < Nn) g_cursor[i0 + 1] = o.y;
    if (i0 + 2 < Nn) g_cursor[i0 + 2] = o.z;
    if (i0 + 3 < Nn) g_cursor[i0 + 3] = o.w;
}

// fused: CSR fill (8 edges/thread, packed) + x init (float4/thread) + W prep
__global__ void k_fillinit(const int* __restrict__ ei, const int* __restrict__ et,
                           const float* __restrict__ be, const float* __restrict__ rel,
                           const int* __restrict__ h_index, const int* __restrict__ r_index,
                           const float* __restrict__ W) {
    const int FILLT = Ee / 8;              // 100000
    const int INITT = Bb * Nn * 16;        // 1600000
    int t = blockIdx.x * blockDim.x + threadIdx.x;
    if (t < FILLT) {
        #pragma unroll
        for (int h = 0; h < 2; h++) {
            int q = t * 2 + h;
            int4 s4 = reinterpret_cast<const int4*>(ei)[q];
            int4 d4 = reinterpret_cast<const int4*>(ei + Ee)[q];
            int4 t4 = reinterpret_cast<const int4*>(et)[q];
            int p0 = atomicAdd(&g_cursor[d4.x], 1);
            int p1 = atomicAdd(&g_cursor[d4.y], 1);
            int p2 = atomicAdd(&g_cursor[d4.z], 1);
            int p3 = atomicAdd(&g_cursor[d4.w], 1);
            g_epk[p0] = (s4.x << 6) | t4.x;
            g_epk[p1] = (s4.y << 6) | t4.y;
            g_epk[p2] = (s4.z << 6) | t4.z;
            g_epk[p3] = (s4.w << 6) | t4.w;
        }
    } else if (t < FILLT + INITT) {
        int idx = t - FILLT;
        int d4i = idx & 15;
        int bn = idx >> 4;
        int b = (bn >= Nn) ? 1 : 0;
        int n = bn - b * Nn;
        float4 v = reinterpret_cast<const float4*>(be)[idx];
        if (n == h_index[b]) {
            float4 q = reinterpret_cast<const float4*>(rel)[((b * Rr + r_index[b]) << 4) + d4i];
            v.x += q.x; v.y += q.y; v.z += q.z; v.w += q.w;
        }
        reinterpret_cast<float4*>(g_x)[idx] = v;
    } else {
        int idx = t - FILLT - INITT;
        if (idx >= Ll * 2 * Dd * Dd) return;
        int l = idx >> 13;
        int rem = idx & 8191;
        int j = rem >> 6;
        int d = rem & 63;
        g_Wt[(l << 13) + d * 128 + (((j >> 2) ^ (d & 31)) << 2) + (j & 3)] = W[idx];
    }
}

// ---------------- gather aggregation (atomic-free) ----------------
// one warp per node, BOTH batches: half-warp = batch, lane owns a float4.
// 8-deep software pipeline: 16 feature LDG.128 in flight per warp.
__global__ __launch_bounds__(256) void k_gather(const float* __restrict__ be,
                                                const float* __restrict__ rel,
                                                const int* __restrict__ h_index,
                                                const int* __restrict__ r_index) {
    int n = blockIdx.x * 8 + (threadIdx.x >> 5);
    if (n >= Nn) return;
    int lane = threadIdx.x & 31;
    int b = lane >> 4;           // batch for this half-warp
    int c = (lane & 15) << 2;    // float4 column offset within D=64

    const size_t row = ((size_t)(b * Nn + n) << 6) + c;
    float4 acc = *reinterpret_cast<const float4*>(&be[row]);
    if (n == h_index[b]) {
        float4 q = __ldg(reinterpret_cast<const float4*>(&rel[((b * Rr + r_index[b]) << 6) + c]));
        acc.x += q.x; acc.y += q.y; acc.z += q.z; acc.w += q.w;
    }

    const float* __restrict__ xb = g_x + ((b * Nn) << 6) + c;
    const float* __restrict__ rb = rel + ((b * Rr) << 6) + c;
    int s = g_deg[n], e = g_deg[n + 1];
    int k = s;

    // packed edge v: x float-offset = v & ~63, rel float-offset = (v & 63) << 6
    #define EDGE_LOAD(vk, xv, rv)                                                      \
        float4 xv = __ldg(reinterpret_cast<const float4*>(xb + ((vk) & ~63)));         \
        float4 rv = __ldg(reinterpret_cast<const float4*>(rb + (((vk) & 63) << 6)));
    #define EDGE_FMA(xv, rv)                                                           \
        acc.x += xv.x * rv.x; acc.y += xv.y * rv.y;                                    \
        acc.z += xv.z * rv.z; acc.w += xv.w * rv.w;

    if (k + 7 < e) {
        int v0 = g_epk[k],     v1 = g_epk[k + 1], v2 = g_epk[k + 2], v3 = g_epk[k + 3];
        int v4 = g_epk[k + 4], v5 = g_epk[k + 5], v6 = g_epk[k + 6], v7 = g_epk[k + 7];
        while (k + 7 < e) {
            int nk = k + 8;
            int q0 = nk     < e ? nk     : e - 1;
            int q1 = nk + 1 < e ? nk + 1 : e - 1;
            int q2 = nk + 2 < e ? nk + 2 : e - 1;
            int q3 = nk + 3 < e ? nk + 3 : e - 1;
            int q4 = nk + 4 < e ? nk + 4 : e - 1;
            int q5 = nk + 5 < e ? nk + 5 : e - 1;
            int q6 = nk + 6 < e ? nk + 6 : e - 1;
            int q7 = nk + 7 < e ? nk + 7 : e - 1;
            int w0 = g_epk[q0], w1 = g_epk[q1], w2 = g_epk[q2], w3 = g_epk[q3];
            int w4 = g_epk[q4], w5 = g_epk[q5], w6 = g_epk[q6], w7 = g_epk[q7];
            EDGE_LOAD(v0, x0, r0)
            EDGE_LOAD(v1, x1, r1)
            EDGE_LOAD(v2, x2, r2)
            EDGE_LOAD(v3, x3, r3)
            EDGE_LOAD(v4, x4, r4)
            EDGE_LOAD(v5, x5, r5)
            EDGE_LOAD(v6, x6, r6)
            EDGE_LOAD(v7, x7, r7)
            EDGE_FMA(x0, r0)
            EDGE_FMA(x1, r1)
            EDGE_FMA(x2, r2)
            EDGE_FMA(x3, r3)
            EDGE_FMA(x4, r4)
            EDGE_FMA(x5, r5)
            EDGE_FMA(x6, r6)
            EDGE_FMA(x7, r7)
            v0 = w0; v1 = w1; v2 = w2; v3 = w3;
            v4 = w4; v5 = w5; v6 = w6; v7 = w7;
            k = nk;
        }
    }
    // tail: batch loads before FMAs (<=7 edges, <=2 latency exposures)
    if (k + 3 < e) {
        int v0 = g_epk[k], v1 = g_epk[k + 1], v2 = g_epk[k + 2], v3 = g_epk[k + 3];
        EDGE_LOAD(v0, x0, r0)
        EDGE_LOAD(v1, x1, r1)
        EDGE_LOAD(v2, x2, r2)
        EDGE_LOAD(v3, x3, r3)
        EDGE_FMA(x0, r0)
        EDGE_FMA(x1, r1)
        EDGE_FMA(x2, r2)
        EDGE_FMA(x3, r3)
        k += 4;
    }
    {
        int rem = e - k;     // 0..3
        if (rem > 0) {
            int v0 = g_epk[k];
            int v1 = g_epk[rem > 1 ? k + 1 : k];
            int v2 = g_epk[rem > 2 ? k + 2 : k];
            EDGE_LOAD(v0, x0, r0)
            EDGE_FMA(x0, r0)
            if (rem > 1) { EDGE_LOAD(v1, x1, r1) EDGE_FMA(x1, r1) }
            if (rem > 2) { EDGE_LOAD(v2, x2, r2) EDGE_FMA(x2, r2) }
        }
    }
    #undef EDGE_LOAD
    #undef EDGE_FMA

    *reinterpret_cast<float4*>(&g_agg[row]) = acc;
}

// ---------------- dense layer: out = relu(LN(concat(x,agg)@W + b)) + x ----------------
// 128 rows/block, 16 rows per warp; lane owns outputs {lane, lane+32}.
// W pre-transposed+swizzled in g_Wt. Packed f32x2 accumulators.
__global__ __launch_bounds__(256, 2) void k_dense(
        const float* __restrict__ Wt, const float* __restrict__ bias,
        const float* __restrict__ gam, const float* __restrict__ bet) {
    extern __shared__ float smem[];
    float* sWt = smem;               // 64 * 128 floats, pre-swizzled (32 KB)
    float* sIn = smem + 64 * 128;    // 128 rows * 128 floats         (64 KB)

    const int tid  = threadIdx.x;
    const int w    = tid >> 5;
    const int lane = tid & 31;
    const int base = blockIdx.x * 128;

    {
        const float4* Wv = reinterpret_cast<const float4*>(Wt);
        float4* sWv = reinterpret_cast<float4*>(sWt);
        #pragma unroll
        for (int k = 0; k < 8; k++) sWv[k * 256 + tid] = Wv[k * 256 + tid];
    }
    {
        float4* sInv = reinterpret_cast<float4*>(sIn);
        #pragma unroll
        for (int k = 0; k < 16; k++) {
            int pos = k * 256 + tid;
            int r   = pos >> 5;
            int c4  = pos & 31;
            int row = base + r;
            float4 v = make_float4(0.f, 0.f, 0.f, 0.f);
            if (row < Bb * Nn) {
                if (c4 < 16)
                    v = *reinterpret_cast<const float4*>(&g_x[((size_t)row << 6) + (c4 << 2)]);
                else
                    v = *reinterpret_cast<const float4*>(&g_agg[((size_t)row << 6) + ((c4 - 16) << 2)]);
            }
            sInv[pos] = v;
        }
    }
    __syncthreads();

    const int r0 = w * 16;
    unsigned long long acc0[16], acc1[16];
    #pragma unroll
    for (int i = 0; i < 16; i++) { acc0[i] = 0ULL; acc1[i] = 0ULL; }

    const float* wb0 = sWt + lane * 128;
    const float* wb1 = sWt + (lane + 32) * 128;

    #pragma unroll 2
    for (int j4 = 0; j4 < 32; j4++) {
        int off = (j4 ^ lane) << 2;
        ulonglong2 wa  = *reinterpret_cast<const ulonglong2*>(wb0 + off);
        ulonglong2 wbv = *reinterpret_cast<const ulonglong2*>(wb1 + off);
        #pragma unroll
        for (int i = 0; i < 16; i++) {
            ulonglong2 in = *reinterpret_cast<const ulonglong2*>(&sIn[(r0 + i) * 128 + (j4 << 2)]);
            FMA2(acc0[i], in.x, wa.x, acc0[i]);
            FMA2(acc0[i], in.y, wa.y, acc0[i]);
            FMA2(acc1[i], in.x, wbv.x, acc1[i]);
            FMA2(acc1[i], in.y, wbv.y, acc1[i]);
        }
    }

    float bx = bias[lane], by = bias[lane + 32];
    float gx = gam[lane],  gy = gam[lane + 32];
    float tx = bet[lane],  ty = bet[lane + 32];

    #pragma unroll
    for (int i = 0; i < 16; i++) {
        int row = base + r0 + i;
        if (row >= Bb * Nn) break;   // uniform across warp
        float2 a0, a1;
        asm("mov.b64 {%0,%1}, %2;" : "=f"(a0.x), "=f"(a0.y) : "l"(acc0[i]));
        asm("mov.b64 {%0,%1}, %2;" : "=f"(a1.x), "=f"(a1.y) : "l"(acc1[i]));
        float o0 = a0.x + a0.y + bx;
        float o1 = a1.x + a1.y + by;

        float s = o0 + o1;
        #pragma unroll
        for (int o = 16; o > 0; o >>= 1) s += __shfl_xor_sync(0xffffffffu, s, o);
        float mu = s * (1.0f / 64.0f);
        float c0 = o0 - mu, c1 = o1 - mu;
        float q = c0 * c0 + c1 * c1;
        #pragma unroll
        for (int o = 16; o > 0; o >>= 1) q += __shfl_xor_sync(0xffffffffu, q, o);
        float inv = rsqrtf(q * (1.0f / 64.0f) + 1e-5f);

        float x0 = sIn[(r0 + i) * 128 + lane];
        float x1 = sIn[(r0 + i) * 128 + lane + 32];
        g_x[((size_t)row << 6) + lane]      = fmaxf(c0 * inv * gx + tx, 0.0f) + x0;
        g_x[((size_t)row << 6) + lane + 32] = fmaxf(c1 * inv * gy + ty, 0.0f) + x1;
    }
}

// ---------------- output MLP ----------------
__global__ void k_out(const int* __restrict__ t_index, const int* __restrict__ r_index,
                      const float* __restrict__ rel,
                      const float* __restrict__ w1, const float* __restrict__ b1,
                      const float* __restrict__ w2, const float* __restrict__ b2,
                      float* __restrict__ out) {
    __shared__ float feat[2 * Dd];
    __shared__ float red[64];
    int b = blockIdx.x >> 5;   // Kk == 32
    int k = blockIdx.x & 31;
    int tid = threadIdx.x;     // 0..63
    int t = t_index[b * Kk + k];
    feat[tid]      = g_x[((size_t)(b * Nn + t)) * Dd + tid];
    feat[Dd + tid] = rel[(b * Rr + r_index[b]) * Dd + tid];
    __syncthreads();
    float h = b1[tid];
    #pragma unroll
    for (int j = 0; j < 2 * Dd; j++) h += feat[j] * w1[j * Dd + tid];
    h = fmaxf(h, 0.0f);
    red[tid] = h * w2[tid];
    __syncthreads();
    if (tid < 32) {
        float v = red[tid] + red[tid + 32];
        #pragma unroll
        for (int o = 16; o > 0; o >>= 1) v += __shfl_xor_sync(0xffffffffu, v, o);
        if (tid == 0) out[blockIdx.x] = v + b2[0];
    }
}

extern "C" void kernel_launch(void* const* d_in, const int* in_sizes, int n_in,
                              void* d_out, int out_size) {
    const int*   edge_index = (const int*)d_in[0];
    const int*   edge_type  = (const int*)d_in[1];
    const int*   h_index    = (const int*)d_in[2];
    const int*   r_index    = (const int*)d_in[3];
    const int*   t_index    = (const int*)d_in[4];
    const float* rel        = (const float*)d_in[5];
    const float* be         = (const float*)d_in[6];
    const float* lW         = (const float*)d_in[7];
    const float* lb         = (const float*)d_in[8];
    const float* lng        = (const float*)d_in[9];
    const float* lnb        = (const float*)d_in[10];
    const float* w1         = (const float*)d_in[11];
    const float* b1         = (const float*)d_in[12];
    const float* w2         = (const float*)d_in[13];
    const float* b2         = (const float*)d_in[14];
    float* out = (float*)d_out;

    const int zero_blocks   = (DEG_PAD / 4 + 255) / 256;                    // 52
    const int hist_blocks   = (Ee / 4 + 255) / 256;                         // 782
    const int fi_threads    = Ee / 8 + Bb * Nn * 16 + Ll * 2 * Dd * Dd;     // ~1.73M
    const int fi_blocks     = (fi_threads + 255) / 256;
    const int gather_blocks = (Nn + 7) / 8;                                 // 6250
    const int dense_blocks  = (Bb * Nn + 127) / 128;                        // 782
    const int dense_smem    = (64 * 128 + 128 * 128) * sizeof(float);       // 96 KB

    static int attr_set = 0;
    if (!attr_set) {
        cudaFuncSetAttribute(k_dense, cudaFuncAttributeMaxDynamicSharedMemorySize, dense_smem);
        attr_set = 1;
    }

    float* Wt; cudaGetSymbolAddress((void**)&Wt, g_Wt);

    // CSR build + x init + W prep (per launch; deterministic inputs)
    k_zero<<<zero_blocks, 256>>>();
    k_hist<<<hist_blocks, 256>>>(edge_index);
    k_scan<<<SCAN_BLOCKS, 1024>>>();
    k_fillinit<<<fi_blocks, 256>>>(edge_index, edge_type, be, rel, h_index, r_index, lW);

    for (int l = 0; l < Ll; l++) {
        k_gather<<<gather_blocks, 256>>>(be, rel, h_index, r_index);
        k_dense<<<dense_blocks, 256, dense_smem>>>(Wt + l * 2 * Dd * Dd, lb + l * Dd,
                                                   lng + l * Dd, lnb + l * Dd);
    }

    k_out<<<Bb * Kk, 64>>>(t_index, r_index, rel, w1, b1, w2, b2, out);
}